// round 8
// baseline (speedup 1.0000x reference)
#include <cuda_runtime.h>
#include <cuda_fp16.h>

#define NROI 4000
#define CCH  64
#define FH   240
#define FW   240
#define NPIX (FH*FW)
#define NBT  (NPIX / 64)   // 900 transpose blocks

// ---------------- scratch (no allocations allowed) ----------------
__device__ __align__(16) __half2 g_fmTh[NPIX * 32]; // HWC fp16 fm (7.4 MB), 32 half2 = 64ch
__device__ float g_pooled[3 * NROI * CCH]; // pooled features per scale
__device__ float g_h[3 * NROI * CCH];      // head outputs per scale
__device__ float g_gpart[NBT * CCH];       // per-block channel partial sums
__device__ float g_bp1eff[128];            // bp1 + head(g) @ P1[192:256]

// ---------------- 1) transpose CHW fp32 -> HWC fp16 + channel partial sums ----------------
__global__ void transpose_kernel(const float* __restrict__ fm) {
    __shared__ float tile[64][65];
    int pix0 = blockIdx.x * 64;
    int tid  = threadIdx.x;
    int lane = tid & 63;     // pixel offset on load
    int grp  = tid >> 6;     // 0..3
    #pragma unroll
    for (int c = grp; c < 64; c += 4)
        tile[c][lane] = fm[c * NPIX + pix0 + lane];
    __syncthreads();
    int c2 = tid & 31;       // channel pair
    int pg = tid >> 5;       // 0..7
    #pragma unroll
    for (int p = pg; p < 64; p += 8)
        g_fmTh[(pix0 + p) * 32 + c2] =
            __floats2half2_rn(tile[2 * c2][p], tile[2 * c2 + 1][p]);
    // per-channel partial sum over this block's 64 pixels
    if (tid < 64) {
        float s = 0.f;
        #pragma unroll 16
        for (int p = 0; p < 64; p++) s += tile[tid][p];
        g_gpart[blockIdx.x * 64 + tid] = s;
    }
}

// ---------------- 2) reduce gmean + fold head(g) into bp1 ----------------
__global__ void head_const_kernel(const float* __restrict__ W1, const float* __restrict__ b1,
                                  const float* __restrict__ W2, const float* __restrict__ b2,
                                  const float* __restrict__ P1, const float* __restrict__ bp1) {
    __shared__ float gs[64];
    __shared__ float part[2][64];
    __shared__ float t[128];
    __shared__ float hg[64];
    int tid = threadIdx.x;  // 128 threads
    {
        int ch = tid & 63;
        int half = tid >> 6;            // 0/1
        int b0 = half * (NBT / 2);
        int b1e = b0 + (NBT / 2);
        float s = 0.f;
        for (int b = b0; b < b1e; b++) s += g_gpart[b * 64 + ch];
        part[half][ch] = s;
    }
    __syncthreads();
    if (tid < 64)
        gs[tid] = (part[0][tid] + part[1][tid]) * (1.0f / (float)NPIX);
    __syncthreads();
    float a = b1[tid];
    #pragma unroll 8
    for (int c = 0; c < 64; c++) a = fmaf(gs[c], W1[c * 128 + tid], a);
    t[tid] = fmaxf(a, 0.f);
    __syncthreads();
    if (tid < 64) {
        float a2 = b2[tid];
        #pragma unroll 8
        for (int k = 0; k < 128; k++) a2 = fmaf(t[k], W2[k * 64 + tid], a2);
        hg[tid] = fmaxf(a2, 0.f);
    }
    __syncthreads();
    float be = bp1[tid];
    #pragma unroll 8
    for (int c = 0; c < 64; c++) be = fmaf(hg[c], P1[(192 + c) * 128 + tid], be);
    g_bp1eff[tid] = be;
}

// ---------------- 3) pooling: 4 samples/warp-iter, HFMA2 bilinear ----------------
template<int S>
__device__ __forceinline__ void pool_roi_v(int n, int lane,
                                           const float* __restrict__ boxes,
                                           float* __restrict__ outb) {
    constexpr int SS = S * S;
    int sub = lane >> 3;   // sample slot 0..3
    int cl  = lane & 7;    // channel group: half2 idx cl*4..cl*4+3 (8 channels)

    float bx1 = __ldg(&boxes[n * 4 + 0]);
    float by1 = __ldg(&boxes[n * 4 + 1]);
    float bx2 = __ldg(&boxes[n * 4 + 2]);
    float by2 = __ldg(&boxes[n * 4 + 3]);
    float nx1 = bx1 * (2.0f / 960.0f) - 1.0f;
    float ny1 = by1 * (2.0f / 960.0f) - 1.0f;
    float nx2 = bx2 * (2.0f / 960.0f) - 1.0f;
    float ny2 = by2 * (2.0f / 960.0f) - 1.0f;
    float cx = (nx1 + nx2) * 0.5f;
    float cy = (ny1 + ny2) * 0.5f;
    float w  = fmaxf(nx2 - nx1, 1e-6f);
    float h  = fmaxf(ny2 - ny1, 1e-6f);
    float stepx = w * (120.0f / (float)S);
    float stepy = h * (120.0f / (float)S);
    float ixb = fmaf(w * 60.0f, (1.0f / (float)S - 1.0f), fmaf(cx, 120.0f, 119.5f));
    float iyb = fmaf(h * 60.0f, (1.0f / (float)S - 1.0f), fmaf(cy, 120.0f, 119.5f));

    float acc[8];
    #pragma unroll
    for (int k = 0; k < 8; k++) acc[k] = 0.f;

    const uint4* fm4 = (const uint4*)g_fmTh;  // one uint4 = 4 half2 = 8 channels

    #pragma unroll 2
    for (int base = 0; base < SS; base += 4) {
        int samp = base + sub;
        bool alive = (samp < SS);
        int sc = alive ? samp : 0;
        int i = sc / S;          // const-divide -> mul/shift
        int j = sc - i * S;
        float ix = fmaf((float)j, stepx, ixb);
        float iy = fmaf((float)i, stepy, iyb);
        float x0f = floorf(ix), y0f = floorf(iy);
        float dx = ix - x0f, dy = iy - y0f;
        int x0 = (int)x0f, y0 = (int)y0f;
        int x1 = x0 + 1,   y1 = y0 + 1;
        float wx0 = ((unsigned)x0 < FW) ? (1.f - dx) : 0.f;
        float wx1 = ((unsigned)x1 < FW) ? dx : 0.f;
        float wy0 = (alive && (unsigned)y0 < FH) ? (1.f - dy) : 0.f;
        float wy1 = (alive && (unsigned)y1 < FH) ? dy : 0.f;
        int xc0 = max(0, min(x0, FW - 1));
        int xc1 = max(0, min(x1, FW - 1));
        int yc0 = max(0, min(y0, FH - 1));
        int yc1 = max(0, min(y1, FH - 1));
        int r0 = yc0 * FW, r1 = yc1 * FW;
        uint4 q00 = __ldg(&fm4[(r0 + xc0) * 8 + cl]);
        uint4 q01 = __ldg(&fm4[(r0 + xc1) * 8 + cl]);
        uint4 q10 = __ldg(&fm4[(r1 + xc0) * 8 + cl]);
        uint4 q11 = __ldg(&fm4[(r1 + xc1) * 8 + cl]);
        __half2 h00 = __float2half2_rn(wy0 * wx0);
        __half2 h01 = __float2half2_rn(wy0 * wx1);
        __half2 h10 = __float2half2_rn(wy1 * wx0);
        __half2 h11 = __float2half2_rn(wy1 * wx1);
        const __half2* f00 = (const __half2*)&q00;
        const __half2* f01 = (const __half2*)&q01;
        const __half2* f10 = (const __half2*)&q10;
        const __half2* f11 = (const __half2*)&q11;
        #pragma unroll
        for (int k = 0; k < 4; k++) {
            __half2 s = __hmul2(h00, f00[k]);
            s = __hfma2(h01, f01[k], s);
            s = __hfma2(h10, f10[k], s);
            s = __hfma2(h11, f11[k], s);
            float2 fs = __half22float2(s);
            acc[2 * k]     += fs.x;
            acc[2 * k + 1] += fs.y;
        }
    }

    #pragma unroll
    for (int k = 0; k < 8; k++) {
        acc[k] += __shfl_down_sync(0xffffffffu, acc[k], 16);
        acc[k] += __shfl_down_sync(0xffffffffu, acc[k], 8);
    }
    if (sub == 0) {
        const float inv = 1.0f / (float)SS;
        float4* o = (float4*)&outb[(size_t)n * 64 + cl * 8];
        o[0] = make_float4(acc[0] * inv, acc[1] * inv, acc[2] * inv, acc[3] * inv);
        o[1] = make_float4(acc[4] * inv, acc[5] * inv, acc[6] * inv, acc[7] * inv);
    }
}

// LPT ordering: heavy S=11 tasks first, S=3 last (tail-filler).
__global__ void pool_all_kernel(const float* __restrict__ boxes) {
    int tid  = threadIdx.x;
    int lane = tid & 31;
    int warp = tid >> 5;
    int task = blockIdx.x * 8 + warp;     // 0..11999
    if (task < NROI) {
        pool_roi_v<11>(task, lane, boxes, g_pooled + (size_t)2 * NROI * CCH);
    } else if (task < 2 * NROI) {
        pool_roi_v<7>(task - NROI, lane, boxes, g_pooled + (size_t)NROI * CCH);
    } else {
        pool_roi_v<3>(task - 2 * NROI, lane, boxes, g_pooled);
    }
}

// ---------------- 4) per-scale MLP head: relu(relu(X@W1+b1)@W2+b2) ----------------
// 32 rows/block, A read directly from gmem (L1-resident); ~81KB smem -> 2 CTAs/SM.
__global__ void head_kernel(const float* __restrict__ W1, const float* __restrict__ b1,
                            const float* __restrict__ W2, const float* __restrict__ b2) {
    extern __shared__ float sh[];
    float* W1s = sh;                 // 64*128 = 8192
    float* W2s = W1s + 8192;         // 128*64 = 8192
    float* Ts  = W2s + 8192;         // 32*128 = 4096
    float* b1s = Ts + 4096;          // 128
    float* b2s = b1s + 128;          // 64

    int tid = threadIdx.x;
    int scale = blockIdx.y;
    int row0 = blockIdx.x * 32;
    const float* X    = g_pooled + (size_t)scale * NROI * CCH;
    float*       Hout = g_h      + (size_t)scale * NROI * CCH;

    {
        const float4* W14 = (const float4*)W1;
        const float4* W24 = (const float4*)W2;
        float4* W1s4 = (float4*)W1s;
        float4* W2s4 = (float4*)W2s;
        #pragma unroll
        for (int idx = tid; idx < 2048; idx += 256) {
            W1s4[idx] = W14[idx];
            W2s4[idx] = W24[idx];
        }
        if (tid < 128) b1s[tid] = b1[tid];
        if (tid < 64)  b2s[tid] = b2[tid];
    }
    __syncthreads();

    int rg = tid >> 4;   // 0..15 -> rows rg*2, rg*2+1
    int cg = tid & 15;

    // phase A: Ts = relu(A@W1 + b1), A from gmem
    float acc[2][8];
    #pragma unroll
    for (int i = 0; i < 2; i++)
        #pragma unroll
        for (int j = 0; j < 8; j++) acc[i][j] = 0.f;

    #pragma unroll 4
    for (int k0 = 0; k0 < 64; k0 += 4) {
        float4 a4[2];
        #pragma unroll
        for (int i = 0; i < 2; i++)
            a4[i] = *(const float4*)&X[(size_t)(row0 + rg * 2 + i) * 64 + k0];
        #pragma unroll
        for (int kk = 0; kk < 4; kk++) {
            float4 w0 = *(const float4*)&W1s[(k0 + kk) * 128 + cg * 8];
            float4 w1 = *(const float4*)&W1s[(k0 + kk) * 128 + cg * 8 + 4];
            float wv[8] = {w0.x, w0.y, w0.z, w0.w, w1.x, w1.y, w1.z, w1.w};
            #pragma unroll
            for (int i = 0; i < 2; i++) {
                float av = (&a4[i].x)[kk];
                #pragma unroll
                for (int j = 0; j < 8; j++)
                    acc[i][j] = fmaf(av, wv[j], acc[i][j]);
            }
        }
    }
    #pragma unroll
    for (int i = 0; i < 2; i++)
        #pragma unroll
        for (int j = 0; j < 8; j++)
            Ts[(rg * 2 + i) * 128 + cg * 8 + j] =
                fmaxf(acc[i][j] + b1s[cg * 8 + j], 0.f);
    __syncthreads();

    // phase B: H = relu(Ts@W2 + b2)
    float acc2[2][4];
    #pragma unroll
    for (int i = 0; i < 2; i++)
        #pragma unroll
        for (int j = 0; j < 4; j++) acc2[i][j] = 0.f;

    #pragma unroll 4
    for (int k0 = 0; k0 < 128; k0 += 4) {
        float4 a4[2];
        #pragma unroll
        for (int i = 0; i < 2; i++)
            a4[i] = *(const float4*)&Ts[(rg * 2 + i) * 128 + k0];
        #pragma unroll
        for (int kk = 0; kk < 4; kk++) {
            float4 wq = *(const float4*)&W2s[(k0 + kk) * 64 + cg * 4];
            float wv[4] = {wq.x, wq.y, wq.z, wq.w};
            #pragma unroll
            for (int i = 0; i < 2; i++) {
                float av = (&a4[i].x)[kk];
                #pragma unroll
                for (int j = 0; j < 4; j++)
                    acc2[i][j] = fmaf(av, wv[j], acc2[i][j]);
            }
        }
    }
    #pragma unroll
    for (int i = 0; i < 2; i++) {
        int r = row0 + rg * 2 + i;
        float4 o;
        o.x = fmaxf(acc2[i][0] + b2s[cg * 4 + 0], 0.f);
        o.y = fmaxf(acc2[i][1] + b2s[cg * 4 + 1], 0.f);
        o.z = fmaxf(acc2[i][2] + b2s[cg * 4 + 2], 0.f);
        o.w = fmaxf(acc2[i][3] + b2s[cg * 4 + 3], 0.f);
        *(float4*)&Hout[(size_t)r * 64 + cg * 4] = o;
    }
}

// ---------------- 5) final: 32 rows/block, h from gmem, ~81KB smem -> 2 CTAs/SM ----------------
__global__ void final_kernel(const float* __restrict__ P1, const float* __restrict__ P2,
                             const float* __restrict__ bp2, float* __restrict__ out) {
    extern __shared__ float sh[];
    float* Ps  = sh;                 // 64*128 chunk = 8192
    float* P2s = Ps + 8192;          // 128*64 = 8192
    float* Ts  = P2s + 8192;         // 32*128 = 4096
    float* be  = Ts + 4096;          // 128
    float* bps = be + 128;           // 64

    int tid = threadIdx.x;
    int row0 = blockIdx.x * 32;
    int rg = tid >> 4;
    int cg = tid & 15;

    {
        const float4* P24 = (const float4*)P2;
        float4* P2s4 = (float4*)P2s;
        #pragma unroll
        for (int idx = tid; idx < 2048; idx += 256) P2s4[idx] = P24[idx];
        if (tid < 128) be[tid] = g_bp1eff[tid];
        if (tid < 64)  bps[tid] = bp2[tid];
    }

    float acc[2][8];
    #pragma unroll
    for (int i = 0; i < 2; i++)
        #pragma unroll
        for (int j = 0; j < 8; j++) acc[i][j] = 0.f;

    for (int kb = 0; kb < 3; kb++) {
        __syncthreads();   // previous chunk's compute done before overwrite
        const float4* P14 = (const float4*)(P1 + (size_t)kb * 64 * 128);
        float4* Ps4 = (float4*)Ps;
        #pragma unroll
        for (int idx = tid; idx < 2048; idx += 256) Ps4[idx] = P14[idx];
        __syncthreads();

        const float* hsrc = g_h + (size_t)kb * NROI * CCH;
        #pragma unroll 4
        for (int k0 = 0; k0 < 64; k0 += 4) {
            float4 a4[2];
            #pragma unroll
            for (int i = 0; i < 2; i++)
                a4[i] = *(const float4*)&hsrc[(size_t)(row0 + rg * 2 + i) * 64 + k0];
            #pragma unroll
            for (int kk = 0; kk < 4; kk++) {
                float4 w0 = *(const float4*)&Ps[(k0 + kk) * 128 + cg * 8];
                float4 w1 = *(const float4*)&Ps[(k0 + kk) * 128 + cg * 8 + 4];
                float wv[8] = {w0.x, w0.y, w0.z, w0.w, w1.x, w1.y, w1.z, w1.w};
                #pragma unroll
                for (int i = 0; i < 2; i++) {
                    float av = (&a4[i].x)[kk];
                    #pragma unroll
                    for (int j = 0; j < 8; j++)
                        acc[i][j] = fmaf(av, wv[j], acc[i][j]);
                }
            }
        }
    }
    #pragma unroll
    for (int i = 0; i < 2; i++)
        #pragma unroll
        for (int j = 0; j < 8; j++)
            Ts[(rg * 2 + i) * 128 + cg * 8 + j] =
                fmaxf(acc[i][j] + be[cg * 8 + j], 0.f);
    __syncthreads();

    float acc2[2][4];
    #pragma unroll
    for (int i = 0; i < 2; i++)
        #pragma unroll
        for (int j = 0; j < 4; j++) acc2[i][j] = 0.f;

    #pragma unroll 4
    for (int k0 = 0; k0 < 128; k0 += 4) {
        float4 a4[2];
        #pragma unroll
        for (int i = 0; i < 2; i++)
            a4[i] = *(const float4*)&Ts[(rg * 2 + i) * 128 + k0];
        #pragma unroll
        for (int kk = 0; kk < 4; kk++) {
            float4 wq = *(const float4*)&P2s[(k0 + kk) * 64 + cg * 4];
            float wv[4] = {wq.x, wq.y, wq.z, wq.w};
            #pragma unroll
            for (int i = 0; i < 2; i++) {
                float av = (&a4[i].x)[kk];
                #pragma unroll
                for (int j = 0; j < 4; j++)
                    acc2[i][j] = fmaf(av, wv[j], acc2[i][j]);
            }
        }
    }
    #pragma unroll
    for (int i = 0; i < 2; i++) {
        int r = row0 + rg * 2 + i;
        float4 o;
        o.x = fmaxf(acc2[i][0] + bps[cg * 4 + 0], 0.f);
        o.y = fmaxf(acc2[i][1] + bps[cg * 4 + 1], 0.f);
        o.z = fmaxf(acc2[i][2] + bps[cg * 4 + 2], 0.f);
        o.w = fmaxf(acc2[i][3] + bps[cg * 4 + 3], 0.f);
        *(float4*)&out[(size_t)r * 64 + cg * 4] = o;
    }
}

// ---------------- launch ----------------
extern "C" void kernel_launch(void* const* d_in, const int* in_sizes, int n_in,
                              void* d_out, int out_size) {
    const float* fm    = (const float*)d_in[0];
    const float* boxes = (const float*)d_in[1];
    const float* W1    = (const float*)d_in[2];
    const float* b1    = (const float*)d_in[3];
    const float* W2    = (const float*)d_in[4];
    const float* b2    = (const float*)d_in[5];
    const float* P1    = (const float*)d_in[6];
    const float* bp1   = (const float*)d_in[7];
    const float* P2    = (const float*)d_in[8];
    const float* bp2   = (const float*)d_in[9];
    float* out = (float*)d_out;

    const int SMEM_H = (8192 + 8192 + 4096 + 128 + 64) * 4;   // 82688 B
    const int SMEM_F = (8192 + 8192 + 4096 + 128 + 64) * 4;   // 82688 B
    cudaFuncSetAttribute(head_kernel,  cudaFuncAttributeMaxDynamicSharedMemorySize, SMEM_H);
    cudaFuncSetAttribute(final_kernel, cudaFuncAttributeMaxDynamicSharedMemorySize, SMEM_F);

    transpose_kernel<<<NBT, 256>>>(fm);
    head_const_kernel<<<1, 128>>>(W1, b1, W2, b2, P1, bp1);

    const int PB = (3 * NROI) / 8;  // 1500 blocks, 8 warps each (exact)
    pool_all_kernel<<<PB, 256>>>(boxes);

    dim3 hgrid(NROI / 32, 3);       // 125 x 3 blocks
    head_kernel<<<hgrid, 256, SMEM_H>>>(W1, b1, W2, b2);

    final_kernel<<<NROI / 32, 256, SMEM_F>>>(P1, P2, bp2, out);
}

// round 9
// speedup vs baseline: 1.0715x; 1.0715x over previous
#include <cuda_runtime.h>
#include <cuda_fp16.h>

#define NROI 4000
#define CCH  64
#define FH   240
#define FW   240
#define NPIX (FH*FW)
#define NBT  (NPIX / 64)   // 900 transpose blocks

// ---------------- scratch (no allocations allowed) ----------------
__device__ __align__(16) __half2 g_fmTh[NPIX * 32]; // HWC fp16 fm (7.4 MB), 32 half2 = 64ch
__device__ float g_pooled[3 * NROI * CCH]; // pooled features per scale
__device__ float g_h[3 * NROI * CCH];      // head outputs per scale
__device__ float g_gpart[NBT * CCH];       // per-block channel partial sums
__device__ float g_bp1eff[128];            // bp1 + head(g) @ P1[192:256]

// ---------------- 1) transpose CHW fp32 -> HWC fp16 + channel partial sums ----------------
__global__ void transpose_kernel(const float* __restrict__ fm) {
    __shared__ float tile[64][65];
    int pix0 = blockIdx.x * 64;
    int tid  = threadIdx.x;
    int lane = tid & 63;     // pixel offset on load
    int grp  = tid >> 6;     // 0..3
    #pragma unroll
    for (int c = grp; c < 64; c += 4)
        tile[c][lane] = fm[c * NPIX + pix0 + lane];
    __syncthreads();
    int c2 = tid & 31;       // channel pair
    int pg = tid >> 5;       // 0..7
    #pragma unroll
    for (int p = pg; p < 64; p += 8)
        g_fmTh[(pix0 + p) * 32 + c2] =
            __floats2half2_rn(tile[2 * c2][p], tile[2 * c2 + 1][p]);
    // per-channel partial sum over this block's 64 pixels
    if (tid < 64) {
        float s = 0.f;
        #pragma unroll 16
        for (int p = 0; p < 64; p++) s += tile[tid][p];
        g_gpart[blockIdx.x * 64 + tid] = s;
    }
}

// ---------------- 2) reduce gmean + fold head(g) into bp1 ----------------
__global__ void head_const_kernel(const float* __restrict__ W1, const float* __restrict__ b1,
                                  const float* __restrict__ W2, const float* __restrict__ b2,
                                  const float* __restrict__ P1, const float* __restrict__ bp1) {
    __shared__ float gs[64];
    __shared__ float part[2][64];
    __shared__ float t[128];
    __shared__ float hg[64];
    int tid = threadIdx.x;  // 128 threads
    {
        int ch = tid & 63;
        int half = tid >> 6;            // 0/1
        int b0 = half * (NBT / 2);
        int b1e = b0 + (NBT / 2);
        float s = 0.f;
        for (int b = b0; b < b1e; b++) s += g_gpart[b * 64 + ch];
        part[half][ch] = s;
    }
    __syncthreads();
    if (tid < 64)
        gs[tid] = (part[0][tid] + part[1][tid]) * (1.0f / (float)NPIX);
    __syncthreads();
    float a = b1[tid];
    #pragma unroll 8
    for (int c = 0; c < 64; c++) a = fmaf(gs[c], W1[c * 128 + tid], a);
    t[tid] = fmaxf(a, 0.f);
    __syncthreads();
    if (tid < 64) {
        float a2 = b2[tid];
        #pragma unroll 8
        for (int k = 0; k < 128; k++) a2 = fmaf(t[k], W2[k * 64 + tid], a2);
        hg[tid] = fmaxf(a2, 0.f);
    }
    __syncthreads();
    float be = bp1[tid];
    #pragma unroll 8
    for (int c = 0; c < 64; c++) be = fmaf(hg[c], P1[(192 + c) * 128 + tid], be);
    g_bp1eff[tid] = be;
}

// ---------------- 3) pooling: 4 samples/warp-iter, HFMA2 bilinear ----------------
template<int S>
__device__ __forceinline__ void pool_roi_v(int n, int lane,
                                           const float* __restrict__ boxes,
                                           float* __restrict__ outb) {
    constexpr int SS = S * S;
    int sub = lane >> 3;   // sample slot 0..3
    int cl  = lane & 7;    // channel group: half2 idx cl*4..cl*4+3 (8 channels)

    float bx1 = __ldg(&boxes[n * 4 + 0]);
    float by1 = __ldg(&boxes[n * 4 + 1]);
    float bx2 = __ldg(&boxes[n * 4 + 2]);
    float by2 = __ldg(&boxes[n * 4 + 3]);
    float nx1 = bx1 * (2.0f / 960.0f) - 1.0f;
    float ny1 = by1 * (2.0f / 960.0f) - 1.0f;
    float nx2 = bx2 * (2.0f / 960.0f) - 1.0f;
    float ny2 = by2 * (2.0f / 960.0f) - 1.0f;
    float cx = (nx1 + nx2) * 0.5f;
    float cy = (ny1 + ny2) * 0.5f;
    float w  = fmaxf(nx2 - nx1, 1e-6f);
    float h  = fmaxf(ny2 - ny1, 1e-6f);
    float stepx = w * (120.0f / (float)S);
    float stepy = h * (120.0f / (float)S);
    float ixb = fmaf(w * 60.0f, (1.0f / (float)S - 1.0f), fmaf(cx, 120.0f, 119.5f));
    float iyb = fmaf(h * 60.0f, (1.0f / (float)S - 1.0f), fmaf(cy, 120.0f, 119.5f));

    float acc[8];
    #pragma unroll
    for (int k = 0; k < 8; k++) acc[k] = 0.f;

    const uint4* fm4 = (const uint4*)g_fmTh;  // one uint4 = 4 half2 = 8 channels

    #pragma unroll 2
    for (int base = 0; base < SS; base += 4) {
        int samp = base + sub;
        bool alive = (samp < SS);
        int sc = alive ? samp : 0;
        int i = sc / S;          // const-divide -> mul/shift
        int j = sc - i * S;
        float ix = fmaf((float)j, stepx, ixb);
        float iy = fmaf((float)i, stepy, iyb);
        float x0f = floorf(ix), y0f = floorf(iy);
        float dx = ix - x0f, dy = iy - y0f;
        int x0 = (int)x0f, y0 = (int)y0f;
        int x1 = x0 + 1,   y1 = y0 + 1;
        float wx0 = ((unsigned)x0 < FW) ? (1.f - dx) : 0.f;
        float wx1 = ((unsigned)x1 < FW) ? dx : 0.f;
        float wy0 = (alive && (unsigned)y0 < FH) ? (1.f - dy) : 0.f;
        float wy1 = (alive && (unsigned)y1 < FH) ? dy : 0.f;
        int xc0 = max(0, min(x0, FW - 1));
        int xc1 = max(0, min(x1, FW - 1));
        int yc0 = max(0, min(y0, FH - 1));
        int yc1 = max(0, min(y1, FH - 1));
        int r0 = yc0 * FW, r1 = yc1 * FW;
        uint4 q00 = __ldg(&fm4[(r0 + xc0) * 8 + cl]);
        uint4 q01 = __ldg(&fm4[(r0 + xc1) * 8 + cl]);
        uint4 q10 = __ldg(&fm4[(r1 + xc0) * 8 + cl]);
        uint4 q11 = __ldg(&fm4[(r1 + xc1) * 8 + cl]);
        __half2 h00 = __float2half2_rn(wy0 * wx0);
        __half2 h01 = __float2half2_rn(wy0 * wx1);
        __half2 h10 = __float2half2_rn(wy1 * wx0);
        __half2 h11 = __float2half2_rn(wy1 * wx1);
        const __half2* f00 = (const __half2*)&q00;
        const __half2* f01 = (const __half2*)&q01;
        const __half2* f10 = (const __half2*)&q10;
        const __half2* f11 = (const __half2*)&q11;
        #pragma unroll
        for (int k = 0; k < 4; k++) {
            __half2 s = __hmul2(h00, f00[k]);
            s = __hfma2(h01, f01[k], s);
            s = __hfma2(h10, f10[k], s);
            s = __hfma2(h11, f11[k], s);
            float2 fs = __half22float2(s);
            acc[2 * k]     += fs.x;
            acc[2 * k + 1] += fs.y;
        }
    }

    #pragma unroll
    for (int k = 0; k < 8; k++) {
        acc[k] += __shfl_down_sync(0xffffffffu, acc[k], 16);
        acc[k] += __shfl_down_sync(0xffffffffu, acc[k], 8);
    }
    if (sub == 0) {
        const float inv = 1.0f / (float)SS;
        float4* o = (float4*)&outb[(size_t)n * 64 + cl * 8];
        o[0] = make_float4(acc[0] * inv, acc[1] * inv, acc[2] * inv, acc[3] * inv);
        o[1] = make_float4(acc[4] * inv, acc[5] * inv, acc[6] * inv, acc[7] * inv);
    }
}

// LPT ordering: heavy S=11 tasks first, S=3 last (tail-filler).
__global__ void pool_all_kernel(const float* __restrict__ boxes) {
    int tid  = threadIdx.x;
    int lane = tid & 31;
    int warp = tid >> 5;
    int task = blockIdx.x * 8 + warp;     // 0..11999
    if (task < NROI) {
        pool_roi_v<11>(task, lane, boxes, g_pooled + (size_t)2 * NROI * CCH);
    } else if (task < 2 * NROI) {
        pool_roi_v<7>(task - NROI, lane, boxes, g_pooled + (size_t)NROI * CCH);
    } else {
        pool_roi_v<3>(task - 2 * NROI, lane, boxes, g_pooled);
    }
}

// ---------------- 4) per-scale MLP head: single reusable weight buffer ----------------
// 32 rows/block; smem ~50KB -> 4 CTAs/SM (32 warps).
__global__ __launch_bounds__(256, 4)
void head_kernel(const float* __restrict__ W1, const float* __restrict__ b1,
                 const float* __restrict__ W2, const float* __restrict__ b2) {
    extern __shared__ float sh[];
    float* Wb  = sh;                 // 8192 floats: W1 (phase A) then W2 (phase B)
    float* Ts  = Wb + 8192;          // 32*128 = 4096
    float* b1s = Ts + 4096;          // 128
    float* b2s = b1s + 128;          // 64

    int tid = threadIdx.x;
    int scale = blockIdx.y;
    int row0 = blockIdx.x * 32;
    const float* X    = g_pooled + (size_t)scale * NROI * CCH;
    float*       Hout = g_h      + (size_t)scale * NROI * CCH;

    {
        const float4* W14 = (const float4*)W1;
        float4* Wb4 = (float4*)Wb;
        #pragma unroll
        for (int idx = tid; idx < 2048; idx += 256) Wb4[idx] = W14[idx];
        if (tid < 128) b1s[tid] = b1[tid];
        if (tid < 64)  b2s[tid] = b2[tid];
    }
    __syncthreads();

    int rg = tid >> 4;   // 0..15 -> rows rg*2, rg*2+1
    int cg = tid & 15;

    // phase A: Ts = relu(A@W1 + b1), A from gmem
    float acc[2][8];
    #pragma unroll
    for (int i = 0; i < 2; i++)
        #pragma unroll
        for (int j = 0; j < 8; j++) acc[i][j] = 0.f;

    #pragma unroll 4
    for (int k0 = 0; k0 < 64; k0 += 4) {
        float4 a4[2];
        #pragma unroll
        for (int i = 0; i < 2; i++)
            a4[i] = *(const float4*)&X[(size_t)(row0 + rg * 2 + i) * 64 + k0];
        #pragma unroll
        for (int kk = 0; kk < 4; kk++) {
            float4 w0 = *(const float4*)&Wb[(k0 + kk) * 128 + cg * 8];
            float4 w1 = *(const float4*)&Wb[(k0 + kk) * 128 + cg * 8 + 4];
            float wv[8] = {w0.x, w0.y, w0.z, w0.w, w1.x, w1.y, w1.z, w1.w};
            #pragma unroll
            for (int i = 0; i < 2; i++) {
                float av = (&a4[i].x)[kk];
                #pragma unroll
                for (int j = 0; j < 8; j++)
                    acc[i][j] = fmaf(av, wv[j], acc[i][j]);
            }
        }
    }
    #pragma unroll
    for (int i = 0; i < 2; i++)
        #pragma unroll
        for (int j = 0; j < 8; j++)
            Ts[(rg * 2 + i) * 128 + cg * 8 + j] =
                fmaxf(acc[i][j] + b1s[cg * 8 + j], 0.f);
    __syncthreads();   // all W1 reads + Ts writes done

    // reload buffer with W2
    {
        const float4* W24 = (const float4*)W2;
        float4* Wb4 = (float4*)Wb;
        #pragma unroll
        for (int idx = tid; idx < 2048; idx += 256) Wb4[idx] = W24[idx];
    }
    __syncthreads();

    // phase B: H = relu(Ts@W2 + b2)
    float acc2[2][4];
    #pragma unroll
    for (int i = 0; i < 2; i++)
        #pragma unroll
        for (int j = 0; j < 4; j++) acc2[i][j] = 0.f;

    #pragma unroll 4
    for (int k0 = 0; k0 < 128; k0 += 4) {
        float4 a4[2];
        #pragma unroll
        for (int i = 0; i < 2; i++)
            a4[i] = *(const float4*)&Ts[(rg * 2 + i) * 128 + k0];
        #pragma unroll
        for (int kk = 0; kk < 4; kk++) {
            float4 wq = *(const float4*)&Wb[(k0 + kk) * 64 + cg * 4];
            float wv[4] = {wq.x, wq.y, wq.z, wq.w};
            #pragma unroll
            for (int i = 0; i < 2; i++) {
                float av = (&a4[i].x)[kk];
                #pragma unroll
                for (int j = 0; j < 4; j++)
                    acc2[i][j] = fmaf(av, wv[j], acc2[i][j]);
            }
        }
    }
    #pragma unroll
    for (int i = 0; i < 2; i++) {
        int r = row0 + rg * 2 + i;
        float4 o;
        o.x = fmaxf(acc2[i][0] + b2s[cg * 4 + 0], 0.f);
        o.y = fmaxf(acc2[i][1] + b2s[cg * 4 + 1], 0.f);
        o.z = fmaxf(acc2[i][2] + b2s[cg * 4 + 2], 0.f);
        o.w = fmaxf(acc2[i][3] + b2s[cg * 4 + 3], 0.f);
        *(float4*)&Hout[(size_t)r * 64 + cg * 4] = o;
    }
}

// ---------------- 5) final: single reusable buffer (P1 chunks, then P2) ----------------
__global__ __launch_bounds__(256, 4)
void final_kernel(const float* __restrict__ P1, const float* __restrict__ P2,
                  const float* __restrict__ bp2, float* __restrict__ out) {
    extern __shared__ float sh[];
    float* Pb  = sh;                 // 8192 floats: P1 chunk / P2
    float* Ts  = Pb + 8192;          // 32*128 = 4096
    float* be  = Ts + 4096;          // 128
    float* bps = be + 128;           // 64

    int tid = threadIdx.x;
    int row0 = blockIdx.x * 32;
    int rg = tid >> 4;
    int cg = tid & 15;

    if (tid < 128) be[tid] = g_bp1eff[tid];
    if (tid < 64)  bps[tid] = bp2[tid];

    float acc[2][8];
    #pragma unroll
    for (int i = 0; i < 2; i++)
        #pragma unroll
        for (int j = 0; j < 8; j++) acc[i][j] = 0.f;

    for (int kb = 0; kb < 3; kb++) {
        __syncthreads();   // previous chunk's reads done before overwrite
        const float4* P14 = (const float4*)(P1 + (size_t)kb * 64 * 128);
        float4* Pb4 = (float4*)Pb;
        #pragma unroll
        for (int idx = tid; idx < 2048; idx += 256) Pb4[idx] = P14[idx];
        __syncthreads();

        const float* hsrc = g_h + (size_t)kb * NROI * CCH;
        #pragma unroll 4
        for (int k0 = 0; k0 < 64; k0 += 4) {
            float4 a4[2];
            #pragma unroll
            for (int i = 0; i < 2; i++)
                a4[i] = *(const float4*)&hsrc[(size_t)(row0 + rg * 2 + i) * 64 + k0];
            #pragma unroll
            for (int kk = 0; kk < 4; kk++) {
                float4 w0 = *(const float4*)&Pb[(k0 + kk) * 128 + cg * 8];
                float4 w1 = *(const float4*)&Pb[(k0 + kk) * 128 + cg * 8 + 4];
                float wv[8] = {w0.x, w0.y, w0.z, w0.w, w1.x, w1.y, w1.z, w1.w};
                #pragma unroll
                for (int i = 0; i < 2; i++) {
                    float av = (&a4[i].x)[kk];
                    #pragma unroll
                    for (int j = 0; j < 8; j++)
                        acc[i][j] = fmaf(av, wv[j], acc[i][j]);
                }
            }
        }
    }
    #pragma unroll
    for (int i = 0; i < 2; i++)
        #pragma unroll
        for (int j = 0; j < 8; j++)
            Ts[(rg * 2 + i) * 128 + cg * 8 + j] =
                fmaxf(acc[i][j] + be[cg * 8 + j], 0.f);
    __syncthreads();   // P1 reads done; Ts ready

    // reload buffer with P2
    {
        const float4* P24 = (const float4*)P2;
        float4* Pb4 = (float4*)Pb;
        #pragma unroll
        for (int idx = tid; idx < 2048; idx += 256) Pb4[idx] = P24[idx];
    }
    __syncthreads();

    float acc2[2][4];
    #pragma unroll
    for (int i = 0; i < 2; i++)
        #pragma unroll
        for (int j = 0; j < 4; j++) acc2[i][j] = 0.f;

    #pragma unroll 4
    for (int k0 = 0; k0 < 128; k0 += 4) {
        float4 a4[2];
        #pragma unroll
        for (int i = 0; i < 2; i++)
            a4[i] = *(const float4*)&Ts[(rg * 2 + i) * 128 + k0];
        #pragma unroll
        for (int kk = 0; kk < 4; kk++) {
            float4 wq = *(const float4*)&Pb[(k0 + kk) * 64 + cg * 4];
            float wv[4] = {wq.x, wq.y, wq.z, wq.w};
            #pragma unroll
            for (int i = 0; i < 2; i++) {
                float av = (&a4[i].x)[kk];
                #pragma unroll
                for (int j = 0; j < 4; j++)
                    acc2[i][j] = fmaf(av, wv[j], acc2[i][j]);
            }
        }
    }
    #pragma unroll
    for (int i = 0; i < 2; i++) {
        int r = row0 + rg * 2 + i;
        float4 o;
        o.x = fmaxf(acc2[i][0] + bps[cg * 4 + 0], 0.f);
        o.y = fmaxf(acc2[i][1] + bps[cg * 4 + 1], 0.f);
        o.z = fmaxf(acc2[i][2] + bps[cg * 4 + 2], 0.f);
        o.w = fmaxf(acc2[i][3] + bps[cg * 4 + 3], 0.f);
        *(float4*)&out[(size_t)r * 64 + cg * 4] = o;
    }
}

// ---------------- launch ----------------
extern "C" void kernel_launch(void* const* d_in, const int* in_sizes, int n_in,
                              void* d_out, int out_size) {
    const float* fm    = (const float*)d_in[0];
    const float* boxes = (const float*)d_in[1];
    const float* W1    = (const float*)d_in[2];
    const float* b1    = (const float*)d_in[3];
    const float* W2    = (const float*)d_in[4];
    const float* b2    = (const float*)d_in[5];
    const float* P1    = (const float*)d_in[6];
    const float* bp1   = (const float*)d_in[7];
    const float* P2    = (const float*)d_in[8];
    const float* bp2   = (const float*)d_in[9];
    float* out = (float*)d_out;

    const int SMEM_M = (8192 + 4096 + 128 + 64) * 4;   // 49920 B
    cudaFuncSetAttribute(head_kernel,  cudaFuncAttributeMaxDynamicSharedMemorySize, SMEM_M);
    cudaFuncSetAttribute(final_kernel, cudaFuncAttributeMaxDynamicSharedMemorySize, SMEM_M);

    transpose_kernel<<<NBT, 256>>>(fm);
    head_const_kernel<<<1, 128>>>(W1, b1, W2, b2, P1, bp1);

    const int PB = (3 * NROI) / 8;  // 1500 blocks, 8 warps each (exact)
    pool_all_kernel<<<PB, 256>>>(boxes);

    dim3 hgrid(NROI / 32, 3);       // 125 x 3 blocks
    head_kernel<<<hgrid, 256, SMEM_M>>>(W1, b1, W2, b2);

    final_kernel<<<NROI / 32, 256, SMEM_M>>>(P1, P2, bp2, out);
}